// round 7
// baseline (speedup 1.0000x reference)
#include <cuda_runtime.h>
#include <cuda_bf16.h>
#include <math.h>
#include <stdint.h>

// Problem constants
#define BSZ 2
#define LSEQ 2048
#define EMB 1024
#define NH 16
#define DH 64
#define BH 32          // BSZ*NH
#define M1 4096        // BSZ*LSEQ
#define N1 3072        // 3*EMB

// Scratch (allocation-free)
__device__ __nv_bfloat16 g_xh[M1*EMB],  g_xl[M1*EMB];
__device__ __nv_bfloat16 g_wih[N1*EMB], g_wil[N1*EMB];
__device__ __nv_bfloat16 g_woh[EMB*EMB],g_wol[EMB*EMB];
__device__ __nv_bfloat16 g_qh[BH*LSEQ*DH], g_ql[BH*LSEQ*DH];
__device__ __nv_bfloat16 g_kh[BH*LSEQ*DH], g_kl[BH*LSEQ*DH];
__device__ __nv_bfloat16 g_vh[BH*LSEQ*DH], g_vl[BH*LSEQ*DH];
__device__ __nv_bfloat16 g_ch[M1*EMB],  g_cl[M1*EMB];

// ---------------------------------------------------------------------------
// PTX helpers
// ---------------------------------------------------------------------------
__device__ __forceinline__ uint32_t smem_u32(const void* p) {
    return (uint32_t)__cvta_generic_to_shared(p);
}
__device__ __forceinline__ void ldm_x4(uint32_t& a0, uint32_t& a1,
                                       uint32_t& a2, uint32_t& a3, uint32_t addr) {
    asm volatile("ldmatrix.sync.aligned.m8n8.x4.shared.b16 {%0,%1,%2,%3},[%4];\n"
                 : "=r"(a0), "=r"(a1), "=r"(a2), "=r"(a3) : "r"(addr));
}
__device__ __forceinline__ void ldm_x4_t(uint32_t& a0, uint32_t& a1,
                                         uint32_t& a2, uint32_t& a3, uint32_t addr) {
    asm volatile("ldmatrix.sync.aligned.m8n8.x4.trans.shared.b16 {%0,%1,%2,%3},[%4];\n"
                 : "=r"(a0), "=r"(a1), "=r"(a2), "=r"(a3) : "r"(addr));
}
__device__ __forceinline__ void mma16816(float* c, const uint32_t* a,
                                         uint32_t b0, uint32_t b1) {
    asm volatile("mma.sync.aligned.m16n8k16.row.col.f32.bf16.bf16.f32 "
                 "{%0,%1,%2,%3},{%4,%5,%6,%7},{%8,%9},{%0,%1,%2,%3};\n"
                 : "+f"(c[0]), "+f"(c[1]), "+f"(c[2]), "+f"(c[3])
                 : "r"(a[0]), "r"(a[1]), "r"(a[2]), "r"(a[3]), "r"(b0), "r"(b1));
}
__device__ __forceinline__ void cp16(void* smem_ptr, const void* gptr) {
    asm volatile("cp.async.cg.shared.global [%0], [%1], 16;\n"
                 :: "r"(smem_u32(smem_ptr)), "l"(gptr));
}
__device__ __forceinline__ void cp_commit() {
    asm volatile("cp.async.commit_group;\n");
}
__device__ __forceinline__ void cp_wait0() {
    asm volatile("cp.async.wait_group 0;\n");
}
__device__ __forceinline__ uint32_t packbf(float lo, float hi) {
    uint32_t r;
    asm("cvt.rn.bf16x2.f32 %0, %1, %2;" : "=r"(r) : "f"(hi), "f"(lo));
    return r;
}
__device__ __forceinline__ void pack_hilo(float v0, float v1,
                                          uint32_t& ph, uint32_t& pl) {
    ph = packbf(v0, v1);
    __nv_bfloat162 h = *(__nv_bfloat162*)&ph;
    pl = packbf(v0 - __bfloat162float(h.x), v1 - __bfloat162float(h.y));
}

// ---------------------------------------------------------------------------
// Prep: fp32 -> bf16 hi/lo split
// ---------------------------------------------------------------------------
__global__ __launch_bounds__(256)
void cvt_hilo(const float* __restrict__ src, int sel, int n4)
{
    int i = blockIdx.x * 256 + threadIdx.x;
    if (i >= n4) return;
    __nv_bfloat16 *dh, *dl;
    if (sel == 0)      { dh = g_xh;  dl = g_xl;  }
    else if (sel == 1) { dh = g_wih; dl = g_wil; }
    else               { dh = g_woh; dl = g_wol; }
    float4 v = ((const float4*)src)[i];
    uint32_t h01, l01, h23, l23;
    pack_hilo(v.x, v.y, h01, l01);
    pack_hilo(v.z, v.w, h23, l23);
    ((uint32_t*)dh)[2*i]   = h01;  ((uint32_t*)dh)[2*i+1] = h23;
    ((uint32_t*)dl)[2*i]   = l01;  ((uint32_t*)dl)[2*i+1] = l23;
}

// ---------------------------------------------------------------------------
// GEMM: C[M,N] = A @ W^T + bias. Split-bf16 3-pass mma, cp.async double buffer.
// BM=128, BN=128, BK=32, 256 threads (8 warps: 4m x 2n, warp = 32m x 64n).
// W-fragments double-buffered in registers (LDSM prefetched one step ahead)
// to cover ldmatrix latency; A-fragments reloaded per kk after the mma block.
// MODE 0: A=g_x*, W=g_wi*; epilogue scatters q(scaled)/k/v hi/lo -> [BH,L,D]
// MODE 1: A=g_c*, W=g_wo*; epilogue writes fp32 C row-major
// ---------------------------------------------------------------------------
#define GST 40
#define GARR 5120           // 128*GST
#define GSTAGE 20480        // 4 arrays per stage
#define GEMM_SMEM (2*GSTAGE*2)  // bytes = 81920

template<int MODE>
__global__ __launch_bounds__(256, 2)
void gemm_mma(const float* __restrict__ bias, float* __restrict__ Cout)
{
    extern __shared__ __nv_bfloat16 smg[];
    const int tid = threadIdx.x, lane = tid & 31, w = tid >> 5;
    const int wm = w >> 1, wn = w & 1;
    const int m0 = blockIdx.y * 128, n0 = blockIdx.x * 128;

    const __nv_bfloat16* Ahg = (MODE == 0) ? g_xh  : g_ch;
    const __nv_bfloat16* Alg = (MODE == 0) ? g_xl  : g_cl;
    const __nv_bfloat16* Whg = (MODE == 0) ? g_wih : g_woh;
    const __nv_bfloat16* Wlg = (MODE == 0) ? g_wil : g_wol;

    const int lr = tid >> 1;            // 0..127
    const int lq = (tid & 1) * 16;      // elem offset 0/16
    const __nv_bfloat16* pAh = Ahg + (size_t)(m0 + lr) * 1024 + lq;
    const __nv_bfloat16* pAl = Alg + (size_t)(m0 + lr) * 1024 + lq;
    const __nv_bfloat16* pWh = Whg + (size_t)(n0 + lr) * 1024 + lq;
    const __nv_bfloat16* pWl = Wlg + (size_t)(n0 + lr) * 1024 + lq;

    auto load_stage = [&](int st, int k0) {
        __nv_bfloat16* b = smg + st * GSTAGE + lr * GST + lq;
        cp16(b,            pAh + k0); cp16(b + 8,          pAh + k0 + 8);
        cp16(b + GARR,     pAl + k0); cp16(b + GARR + 8,   pAl + k0 + 8);
        cp16(b + 2*GARR,   pWh + k0); cp16(b + 2*GARR + 8, pWh + k0 + 8);
        cp16(b + 3*GARR,   pWl + k0); cp16(b + 3*GARR + 8, pWl + k0 + 8);
        cp_commit();
    };

    float c[2][8][4];
#pragma unroll
    for (int a = 0; a < 2; a++)
#pragma unroll
        for (int b = 0; b < 8; b++)
#pragma unroll
            for (int d = 0; d < 4; d++) c[a][b][d] = 0.f;

    // precomputed ldmatrix row/col components
    const int arow = wm * 32 + (lane & 15);
    const int akof = (lane >> 4) << 3;
    const int wrow = wn * 64 + ((lane >> 4) << 3) + (lane & 7);
    const int wkof = ((lane >> 3) & 1) * 8;

    load_stage(0, 0);

    for (int it = 0; it < 32; it++) {
        cp_wait0();
        __syncthreads();
        if (it < 31) load_stage((it + 1) & 1, (it + 1) * 32);

        __nv_bfloat16* Ah = smg + (it & 1) * GSTAGE;
        __nv_bfloat16* Al = Ah + GARR;
        __nv_bfloat16* Wh = Ah + 2*GARR;
        __nv_bfloat16* Wl = Ah + 3*GARR;

        uint32_t aH[2][4], aL[2][4];
        uint32_t bf[2][8];                 // W-fragment double buffer

        auto ldA = [&](int kk) {
#pragma unroll
            for (int mt = 0; mt < 2; mt++) {
                int off = (arow + mt * 16) * GST + kk * 16 + akof;
                ldm_x4(aH[mt][0], aH[mt][1], aH[mt][2], aH[mt][3],
                       smem_u32(&Ah[off]));
                ldm_x4(aL[mt][0], aL[mt][1], aL[mt][2], aL[mt][3],
                       smem_u32(&Al[off]));
            }
        };
        auto ldW = [&](int kk, int np, uint32_t* dst) {
            int off = (wrow + np * 16) * GST + kk * 16 + wkof;
            ldm_x4(dst[0], dst[1], dst[2], dst[3], smem_u32(&Wh[off]));
            ldm_x4(dst[4], dst[5], dst[6], dst[7], smem_u32(&Wl[off]));
        };

        ldA(0);
        ldW(0, 0, bf[0]);

#pragma unroll
        for (int step = 0; step < 8; step++) {
            const int np = step & 3;
            uint32_t* bc = bf[step & 1];
            // prefetch next step's W fragments before the mma block
            if (step < 7) ldW((step + 1) >> 2, (step + 1) & 3, bf[(step + 1) & 1]);
            // pass HH (4 independent accumulators)
            mma16816(c[0][2*np],   aH[0], bc[0], bc[1]);
            mma16816(c[0][2*np+1], aH[0], bc[2], bc[3]);
            mma16816(c[1][2*np],   aH[1], bc[0], bc[1]);
            mma16816(c[1][2*np+1], aH[1], bc[2], bc[3]);
            // pass HL
            mma16816(c[0][2*np],   aH[0], bc[4], bc[5]);
            mma16816(c[0][2*np+1], aH[0], bc[6], bc[7]);
            mma16816(c[1][2*np],   aH[1], bc[4], bc[5]);
            mma16816(c[1][2*np+1], aH[1], bc[6], bc[7]);
            // pass LH
            mma16816(c[0][2*np],   aL[0], bc[0], bc[1]);
            mma16816(c[0][2*np+1], aL[0], bc[2], bc[3]);
            mma16816(c[1][2*np],   aL[1], bc[0], bc[1]);
            mma16816(c[1][2*np+1], aL[1], bc[2], bc[3]);
            // A fragments for kk=1, loaded after their last kk=0 use
            if (step == 3) ldA(1);
        }
    }

    // Epilogue
    const int rA = lane >> 2, colq = (lane & 3) * 2;
#pragma unroll
    for (int mt = 0; mt < 2; mt++) {
#pragma unroll
        for (int np = 0; np < 4; np++) {
#pragma unroll
            for (int cc = 0; cc < 2; cc++) {
                int n = n0 + wn * 64 + np * 16 + cc * 8 + colq;
                int mrow = m0 + wm * 32 + mt * 16 + rA;
                float bv0 = bias[n], bv1 = bias[n + 1];
                float* cp = c[mt][2*np + cc];
                float v0 = cp[0] + bv0, v1 = cp[1] + bv1;
                float v2 = cp[2] + bv0, v3 = cp[3] + bv1;
                if (MODE == 0) {
                    int which = n >> 10;
                    int e = n & 1023, hh = e >> 6, d = e & 63;
                    if (which == 0) { v0*=0.125f; v1*=0.125f; v2*=0.125f; v3*=0.125f; }
                    int b = mrow >> 11;
                    size_t dA = (((size_t)(b * NH + hh)) * LSEQ + (mrow & 2047)) * DH + d;
                    size_t dB = dA + 8 * DH;
                    uint32_t h01, l01, h23, l23;
                    pack_hilo(v0, v1, h01, l01);
                    pack_hilo(v2, v3, h23, l23);
                    __nv_bfloat16 *dh, *dl;
                    if (which == 0)      { dh = g_qh; dl = g_ql; }
                    else if (which == 1) { dh = g_kh; dl = g_kl; }
                    else                 { dh = g_vh; dl = g_vl; }
                    *(uint32_t*)(dh + dA) = h01;
                    *(uint32_t*)(dl + dA) = l01;
                    *(uint32_t*)(dh + dB) = h23;
                    *(uint32_t*)(dl + dB) = l23;
                } else {
                    *(float2*)(Cout + (size_t)mrow * EMB + n) = make_float2(v0, v1);
                    *(float2*)(Cout + (size_t)(mrow + 8) * EMB + n) = make_float2(v2, v3);
                }
            }
        }
    }
}

// ---------------------------------------------------------------------------
// Flash attention: QK 3-pass split bf16, PV 3-pass with register hi/lo P,
// K/V double-buffered via cp.async, bias loaded as S accumulator init.
// Grid (L/128, BH), 256 threads, 2 CTAs/SM. Br=128 (16 rows/warp), Bc=64.
// ---------------------------------------------------------------------------
#define AST 72
#define KARR 4608          // 64*AST
#define KSTAGE 18432       // 4 arrays
#define ATTN_SMEM 110592

__global__ __launch_bounds__(256, 2)
void attn_mma(const float* __restrict__ keb)
{
    extern __shared__ __nv_bfloat16 sma[];
    __nv_bfloat16* Qh = sma;
    __nv_bfloat16* Ql = sma + 9216;
    __nv_bfloat16* KVbase = sma + 18432;

    const int tid = threadIdx.x, lane = tid & 31, w = tid >> 5;
    const int bh = blockIdx.y;
    const int q0 = blockIdx.x * 128;
    const size_t hb = (size_t)bh * LSEQ * DH;
    const float* Bg = keb + (size_t)bh * LSEQ * LSEQ;

    const int lr = tid >> 2;           // 0..63
    const int lq = (tid & 3) * 16;     // 0,16,32,48
    const __nv_bfloat16* pKh = g_kh + hb + (size_t)lr * 64 + lq;
    const __nv_bfloat16* pKl = g_kl + hb + (size_t)lr * 64 + lq;
    const __nv_bfloat16* pVh = g_vh + hb + (size_t)lr * 64 + lq;
    const __nv_bfloat16* pVl = g_vl + hb + (size_t)lr * 64 + lq;

    auto load_kv = [&](int st, int k0) {
        __nv_bfloat16* b = KVbase + st * KSTAGE + lr * AST + lq;
        size_t off = (size_t)k0 * 64;
        cp16(b,            pKh + off); cp16(b + 8,          pKh + off + 8);
        cp16(b + KARR,     pKl + off); cp16(b + KARR + 8,   pKl + off + 8);
        cp16(b + 2*KARR,   pVh + off); cp16(b + 2*KARR + 8, pVh + off + 8);
        cp16(b + 3*KARR,   pVl + off); cp16(b + 3*KARR + 8, pVl + off + 8);
        cp_commit();
    };

    load_kv(0, 0);

    // Q tile -> smem
#pragma unroll
    for (int i = 0; i < 4; i++) {
        int id = tid + i * 256;
        int r = id >> 3, c8 = (id & 7) * 8;
        size_t src = hb + (size_t)(q0 + r) * DH + c8;
        *(uint4*)&Qh[r * AST + c8] = *(const uint4*)(g_qh + src);
        *(uint4*)&Ql[r * AST + c8] = *(const uint4*)(g_ql + src);
    }
    __syncthreads();

    uint32_t qH[4][4], qL[4][4];
#pragma unroll
    for (int kk = 0; kk < 4; kk++) {
        int row = w * 16 + (lane & 15);
        int kof = kk * 16 + ((lane >> 4) << 3);
        ldm_x4(qH[kk][0], qH[kk][1], qH[kk][2], qH[kk][3], smem_u32(&Qh[row * AST + kof]));
        ldm_x4(qL[kk][0], qL[kk][1], qL[kk][2], qL[kk][3], smem_u32(&Ql[row * AST + kof]));
    }

    float o[8][4];
#pragma unroll
    for (int j = 0; j < 8; j++)
#pragma unroll
        for (int d = 0; d < 4; d++) o[j][d] = 0.f;
    float mA = -INFINITY, mB = -INFINITY, lA = 0.f, lB = 0.f;

    const int rA = lane >> 2, colq = (lane & 3) * 2;
    const int qrowA = q0 + w * 16 + rA;
    const float* Br0 = Bg + (size_t)qrowA * LSEQ + colq;
    const float* Br1 = Bg + (size_t)(qrowA + 8) * LSEQ + colq;

    for (int it = 0; it < 32; it++) {
        const int k0 = it * 64;

        // S init = bias (LDG latency overlapped with cp wait + kv issue)
        float s[8][4];
#pragma unroll
        for (int j = 0; j < 8; j++) {
            float2 b0 = *(const float2*)(Br0 + k0 + j * 8);
            float2 b1 = *(const float2*)(Br1 + k0 + j * 8);
            s[j][0] = b0.x; s[j][1] = b0.y; s[j][2] = b1.x; s[j][3] = b1.y;
        }

        cp_wait0();
        __syncthreads();
        if (it < 31) load_kv((it + 1) & 1, k0 + 64);

        __nv_bfloat16* Kh = KVbase + (it & 1) * KSTAGE;
        __nv_bfloat16* Kl = Kh + KARR;
        __nv_bfloat16* Vh = Kh + 2*KARR;
        __nv_bfloat16* Vl = Kh + 3*KARR;

        // S += Q K^T (3-pass)
#pragma unroll
        for (int kk = 0; kk < 4; kk++) {
#pragma unroll
            for (int np = 0; np < 4; np++) {
                int row = np * 16 + ((lane >> 4) << 3) + (lane & 7);
                int kof = kk * 16 + ((lane >> 3) & 1) * 8;
                uint32_t bh0, bh1, bh2, bh3, bl0, bl1, bl2, bl3;
                ldm_x4(bh0, bh1, bh2, bh3, smem_u32(&Kh[row * AST + kof]));
                ldm_x4(bl0, bl1, bl2, bl3, smem_u32(&Kl[row * AST + kof]));
                mma16816(s[2*np],   qH[kk], bh0, bh1);
                mma16816(s[2*np+1], qH[kk], bh2, bh3);
                mma16816(s[2*np],   qH[kk], bl0, bl1);
                mma16816(s[2*np+1], qH[kk], bl2, bl3);
                mma16816(s[2*np],   qL[kk], bh0, bh1);
                mma16816(s[2*np+1], qL[kk], bh2, bh3);
            }
        }

        // online softmax
        float mxA = -INFINITY, mxB = -INFINITY;
#pragma unroll
        for (int j = 0; j < 8; j++) {
            mxA = fmaxf(mxA, fmaxf(s[j][0], s[j][1]));
            mxB = fmaxf(mxB, fmaxf(s[j][2], s[j][3]));
        }
        mxA = fmaxf(mxA, __shfl_xor_sync(0xffffffffu, mxA, 1));
        mxA = fmaxf(mxA, __shfl_xor_sync(0xffffffffu, mxA, 2));
        mxB = fmaxf(mxB, __shfl_xor_sync(0xffffffffu, mxB, 1));
        mxB = fmaxf(mxB, __shfl_xor_sync(0xffffffffu, mxB, 2));

        float mnA = fmaxf(mA, mxA), mnB = fmaxf(mB, mxB);
        float cA = __expf(mA - mnA), cB = __expf(mB - mnB);
        mA = mnA; mB = mnB;

        float sA = 0.f, sB = 0.f;
#pragma unroll
        for (int j = 0; j < 8; j++) {
            s[j][0] = __expf(s[j][0] - mnA);
            s[j][1] = __expf(s[j][1] - mnA);
            s[j][2] = __expf(s[j][2] - mnB);
            s[j][3] = __expf(s[j][3] - mnB);
            sA += s[j][0] + s[j][1];
            sB += s[j][2] + s[j][3];
        }
        sA += __shfl_xor_sync(0xffffffffu, sA, 1);
        sA += __shfl_xor_sync(0xffffffffu, sA, 2);
        sB += __shfl_xor_sync(0xffffffffu, sB, 1);
        sB += __shfl_xor_sync(0xffffffffu, sB, 2);
        lA = lA * cA + sA;
        lB = lB * cB + sB;

#pragma unroll
        for (int j = 0; j < 8; j++) {
            o[j][0] *= cA; o[j][1] *= cA; o[j][2] *= cB; o[j][3] *= cB;
        }

        // O += P V : P split hi/lo in registers, 3-pass
#pragma unroll
        for (int kk = 0; kk < 4; kk++) {
            uint32_t pH[4], pL[4];
            pack_hilo(s[2*kk][0],   s[2*kk][1],   pH[0], pL[0]);
            pack_hilo(s[2*kk][2],   s[2*kk][3],   pH[1], pL[1]);
            pack_hilo(s[2*kk+1][0], s[2*kk+1][1], pH[2], pL[2]);
            pack_hilo(s[2*kk+1][2], s[2*kk+1][3], pH[3], pL[3]);
#pragma unroll
            for (int np = 0; np < 4; np++) {
                int vrow = kk * 16 + ((lane >> 3) & 1) * 8 + (lane & 7);
                int vcol = np * 16 + (lane >> 4) * 8;
                uint32_t vh0, vh1, vh2, vh3, vl0, vl1, vl2, vl3;
                ldm_x4_t(vh0, vh1, vh2, vh3, smem_u32(&Vh[vrow * AST + vcol]));
                ldm_x4_t(vl0, vl1, vl2, vl3, smem_u32(&Vl[vrow * AST + vcol]));
                mma16816(o[2*np],   pH, vh0, vh1);
                mma16816(o[2*np+1], pH, vh2, vh3);
                mma16816(o[2*np],   pH, vl0, vl1);
                mma16816(o[2*np+1], pH, vl2, vl3);
                mma16816(o[2*np],   pL, vh0, vh1);
                mma16816(o[2*np+1], pL, vh2, vh3);
            }
        }
    }

    // Epilogue: ctx hi/lo in [B, L, E]
    const float invA = 1.f / lA, invB = 1.f / lB;
    const int b = bh >> 4, h = bh & 15;
#pragma unroll
    for (int j = 0; j < 8; j++) {
        int d = j * 8 + colq;
        size_t eA = ((size_t)b * LSEQ + qrowA) * EMB + h * 64 + d;
        size_t eB = eA + (size_t)8 * EMB;
        uint32_t h01, l01, h23, l23;
        pack_hilo(o[j][0] * invA, o[j][1] * invA, h01, l01);
        pack_hilo(o[j][2] * invB, o[j][3] * invB, h23, l23);
        *(uint32_t*)(g_ch + eA) = h01;
        *(uint32_t*)(g_cl + eA) = l01;
        *(uint32_t*)(g_ch + eB) = h23;
        *(uint32_t*)(g_cl + eB) = l23;
    }
}

// ---------------------------------------------------------------------------
extern "C" void kernel_launch(void* const* d_in, const int* in_sizes, int n_in,
                              void* d_out, int out_size)
{
    const float* X     = (const float*)d_in[0];
    const float* keb   = (const float*)d_in[1];
    const float* w_in  = (const float*)d_in[2];
    const float* b_in  = (const float*)d_in[3];
    const float* w_out = (const float*)d_in[4];
    const float* b_out = (const float*)d_in[5];
    float* out = (float*)d_out;

    cudaFuncSetAttribute(gemm_mma<0>, cudaFuncAttributeMaxDynamicSharedMemorySize, GEMM_SMEM);
    cudaFuncSetAttribute(gemm_mma<1>, cudaFuncAttributeMaxDynamicSharedMemorySize, GEMM_SMEM);
    cudaFuncSetAttribute(attn_mma,    cudaFuncAttributeMaxDynamicSharedMemorySize, ATTN_SMEM);

    // 0) Split inputs into bf16 hi/lo
    cvt_hilo<<<4096, 256>>>(X,     0, M1*EMB/4);
    cvt_hilo<<<3072, 256>>>(w_in,  1, N1*EMB/4);
    cvt_hilo<<<1024, 256>>>(w_out, 2, EMB*EMB/4);

    // 1) QKV projection
    gemm_mma<0><<<dim3(N1/128, M1/128), 256, GEMM_SMEM>>>(b_in, nullptr);

    // 2) Attention with additive ke_bias
    attn_mma<<<dim3(LSEQ/128, BH), 256, ATTN_SMEM>>>(keb);

    // 3) Output projection
    gemm_mma<1><<<dim3(EMB/128, M1/128), 256, GEMM_SMEM>>>(b_out, out);
}